// round 5
// baseline (speedup 1.0000x reference)
#include <cuda_runtime.h>
#include <cuda_fp16.h>
#include <math.h>
#include <stdint.h>

#define EMBED 1024
#define HEADS 16
#define HEAD_DIM 64
#define HIDDEN 4096
#define BATCH 2
#define SEQ 2048
#define NTOK (BATCH*SEQ)   // 4096
#define EPS 1e-6f
#define QSCALE 0.1803368801111204f   // 1/sqrt(64) * log2(e)

// ================= scratch (device globals; no allocation) =================
__device__ __align__(1024) float g_x1  [NTOK * EMBED];

__device__ __align__(1024) __half g_xn  [NTOK * EMBED];        // LN outputs (fp16)
__device__ __align__(1024) __half g_qkv_hi[NTOK * 3 * EMBED];
__device__ __align__(1024) __half g_qkv_lo[NTOK * 3 * EMBED];
__device__ __align__(1024) __half g_att [NTOK * EMBED];
__device__ __align__(1024) __half g_h   [NTOK * HIDDEN];

__device__ __align__(1024) __half g_qkvw_hi [3*EMBED*EMBED];
__device__ __align__(1024) __half g_qkvw_lo [3*EMBED*EMBED];
__device__ __align__(1024) __half g_projw_hi[EMBED*EMBED];
__device__ __align__(1024) __half g_projw_lo[EMBED*EMBED];
__device__ __align__(1024) __half g_fc1w_hi [HIDDEN*EMBED];
__device__ __align__(1024) __half g_fc1w_lo [HIDDEN*EMBED];
__device__ __align__(1024) __half g_fc2w_hi [EMBED*HIDDEN];
__device__ __align__(1024) __half g_fc2w_lo [EMBED*HIDDEN];

// ================= helpers =================
__device__ __forceinline__ uint32_t smem_u32(const void* p) {
    uint32_t a;
    asm("{ .reg .u64 t; cvta.to.shared.u64 t, %1; cvt.u32.u64 %0, t; }" : "=r"(a) : "l"(p));
    return a;
}
#define CP16(dst, src) \
    asm volatile("cp.async.cg.shared.global [%0], [%1], 16;" :: "r"(dst), "l"(src) : "memory")
#define CP_COMMIT() asm volatile("cp.async.commit_group;" ::: "memory")

#define SWZ(x) ((x) ^ (((x) >> 3) & 0x70))

__device__ __forceinline__ void ldsm_x4(uint32_t addr, uint32_t& r0, uint32_t& r1,
                                        uint32_t& r2, uint32_t& r3) {
    asm volatile("ldmatrix.sync.aligned.m8n8.x4.shared.b16 {%0,%1,%2,%3}, [%4];"
                 : "=r"(r0), "=r"(r1), "=r"(r2), "=r"(r3) : "r"(addr));
}
__device__ __forceinline__ void ldsm_x4_t(uint32_t addr, uint32_t& r0, uint32_t& r1,
                                          uint32_t& r2, uint32_t& r3) {
    asm volatile("ldmatrix.sync.aligned.m8n8.x4.trans.shared.b16 {%0,%1,%2,%3}, [%4];"
                 : "=r"(r0), "=r"(r1), "=r"(r2), "=r"(r3) : "r"(addr));
}
__device__ __forceinline__ void mma16816(float* d, const uint32_t* a, const uint32_t* b) {
    asm volatile("mma.sync.aligned.m16n8k16.row.col.f32.f16.f16.f32 "
        "{%0,%1,%2,%3}, {%4,%5,%6,%7}, {%8,%9}, {%0,%1,%2,%3};"
        : "+f"(d[0]), "+f"(d[1]), "+f"(d[2]), "+f"(d[3])
        : "r"(a[0]), "r"(a[1]), "r"(a[2]), "r"(a[3]), "r"(b[0]), "r"(b[1]));
}
__device__ __forceinline__ float ex2f(float x) {
    float y; asm("ex2.approx.f32 %0, %1;" : "=f"(y) : "f"(x)); return y;
}

__device__ __forceinline__ uint32_t pack2h(float a, float b) {
    __half2 t = __floats2half2_rn(a, b);
    return *(uint32_t*)&t;
}
__device__ __forceinline__ void split2h(float x, float y, uint32_t& ph, uint32_t& pl) {
    __half hx = __float2half_rn(x), hy = __float2half_rn(y);
    __half2 hh = __halves2half2(hx, hy);
    ph = *(uint32_t*)&hh;
    pl = pack2h(x - __half2float(hx), y - __half2float(hy));
}

// ================= weight fp32 -> fp16 hi/lo =================
__global__ void __launch_bounds__(256) cvt_kernel(const float* __restrict__ in,
                                                  __half* __restrict__ hi,
                                                  __half* __restrict__ lo,
                                                  int n4)
{
    int i = blockIdx.x * 256 + threadIdx.x;
    if (i >= n4) return;
    float4 v = ((const float4*)in)[i];
    uint2 ph, pl;
    split2h(v.x, v.y, ph.x, pl.x);
    split2h(v.z, v.w, ph.y, pl.y);
    ((uint2*)hi)[i] = ph;
    ((uint2*)lo)[i] = pl;
}

// ================= LayerNorm -> fp16 =================
__global__ void __launch_bounds__(256) ln_kernel(const float* __restrict__ in,
                                                 const float* __restrict__ w,
                                                 const float* __restrict__ b,
                                                 __half* __restrict__ outp)
{
    __shared__ float red[8];
    __shared__ float s_mu, s_rs;
    int row = blockIdx.x;
    int tid = threadIdx.x;
    const float4* ip = (const float4*)(in + (size_t)row * EMBED);
    float4 v = ip[tid];

    float s = v.x + v.y + v.z + v.w;
    #pragma unroll
    for (int o = 16; o; o >>= 1) s += __shfl_xor_sync(0xffffffffu, s, o);
    if ((tid & 31) == 0) red[tid >> 5] = s;
    __syncthreads();
    if (tid == 0) {
        float tot = 0.f;
        #pragma unroll
        for (int i = 0; i < 8; i++) tot += red[i];
        s_mu = tot * (1.0f / EMBED);
    }
    __syncthreads();
    float mu = s_mu;

    float dx = v.x - mu, dy = v.y - mu, dz = v.z - mu, dw = v.w - mu;
    float s2 = dx*dx + dy*dy + dz*dz + dw*dw;
    #pragma unroll
    for (int o = 16; o; o >>= 1) s2 += __shfl_xor_sync(0xffffffffu, s2, o);
    __syncthreads();
    if ((tid & 31) == 0) red[tid >> 5] = s2;
    __syncthreads();
    if (tid == 0) {
        float tot = 0.f;
        #pragma unroll
        for (int i = 0; i < 8; i++) tot += red[i];
        s_rs = rsqrtf(tot * (1.0f / EMBED) + EPS);
    }
    __syncthreads();
    float rs = s_rs;

    float4 wv = ((const float4*)w)[tid];
    float4 bv = ((const float4*)b)[tid];
    uint2 o4;
    o4.x = pack2h(dx * rs * wv.x + bv.x, dy * rs * wv.y + bv.y);
    o4.y = pack2h(dz * rs * wv.z + bv.z, dw * rs * wv.w + bv.w);
    ((uint2*)(outp + (size_t)row * EMBED))[tid] = o4;
}

// ================= HMMA GEMM (NT, fp16 2-product, fp32 accum) =================
// C[m,n] = sum_k A[m,k]*(Bhi+Blo)[n,k] + bias[n]
// EPI: 1 = bias + residual (fp32), 2 = bias + gelu (fp16), 3 = bias + qscale (fp16 hi/lo)
#define T16K 16384
#define STG 49152     // 3 tiles * 16KB

template<int EPI>
__global__ void __launch_bounds__(256, 1) mm_kernel(
    const __half* __restrict__ A,
    const __half* __restrict__ Bhi, const __half* __restrict__ Blo,
    const float* __restrict__ bias, const float* __restrict__ res,
    float* __restrict__ C, __half* __restrict__ Co,
    __half* __restrict__ Chi, __half* __restrict__ Clo,
    int M, int N, int K)
{
    extern __shared__ char smem[];   // 3 stages * 48KB = 144KB
    uint32_t sb = smem_u32(smem);
    int tid = threadIdx.x;
    int bm = blockIdx.x * 128;
    int bn = blockIdx.y * 128;
    int lane = tid & 31, w = tid >> 5;
    int wm = w & 1, wn = w >> 1;     // warp grid 2(m) x 4(n)

    int cc = tid & 7;
    int r0 = tid >> 3;
    const char* pA  = (const char*)(A   + (size_t)(bm + r0) * K) + cc * 16;
    const char* pBh = (const char*)(Bhi + (size_t)(bn + r0) * K) + cc * 16;
    const char* pBl = (const char*)(Blo + (size_t)(bn + r0) * K) + cc * 16;
    size_t rowblk = (size_t)K * 64;  // 32 rows * K * 2B
    uint32_t d0[4];
    #pragma unroll
    for (int j = 0; j < 4; j++) d0[j] = SWZ((uint32_t)((r0 + 32*j) * 128 + cc * 16));

    float acc[4][4][4];
    #pragma unroll
    for (int i = 0; i < 4; i++)
        #pragma unroll
        for (int j = 0; j < 4; j++)
            #pragma unroll
            for (int q = 0; q < 4; q++) acc[i][j][q] = 0.f;

    int nCh = K >> 6;

    // prologue: prefetch chunks 0 and 1
    #pragma unroll
    for (int pc = 0; pc < 2; pc++) {
        uint32_t st = sb + (uint32_t)pc * STG;
        size_t koff = (size_t)pc * 128;
        #pragma unroll
        for (int j = 0; j < 4; j++) {
            size_t so = (size_t)j * rowblk + koff;
            CP16(st + 0*T16K + d0[j], pA  + so);
            CP16(st + 1*T16K + d0[j], pBh + so);
            CP16(st + 2*T16K + d0[j], pBl + so);
        }
        CP_COMMIT();
    }

    for (int c = 0; c < nCh; c++) {
        if (c + 1 < nCh) asm volatile("cp.async.wait_group 1;" ::: "memory");
        else             asm volatile("cp.async.wait_group 0;" ::: "memory");
        __syncthreads();

        if (c + 2 < nCh) {
            int sidx = (c + 2) % 3;
            uint32_t st = sb + (uint32_t)sidx * STG;
            size_t koff = (size_t)(c + 2) * 128;
            #pragma unroll
            for (int j = 0; j < 4; j++) {
                size_t so = (size_t)j * rowblk + koff;
                CP16(st + 0*T16K + d0[j], pA  + so);
                CP16(st + 1*T16K + d0[j], pBh + so);
                CP16(st + 2*T16K + d0[j], pBl + so);
            }
            CP_COMMIT();
        }

        uint32_t st = sb + (uint32_t)(c % 3) * STG;
        uint32_t As = st, Bhs = st + T16K, Bls = st + 2*T16K;

        #pragma unroll
        for (int ks = 0; ks < 4; ks++) {
            uint32_t af[4][4], bhi[4][2], blo[4][2];
            #pragma unroll
            for (int i = 0; i < 4; i++) {
                int row = wm*64 + i*16 + (lane & 15);
                int c16 = ks*2 + (lane >> 4);
                uint32_t off = SWZ((uint32_t)(row * 128 + c16 * 16));
                ldsm_x4(As + off, af[i][0], af[i][1], af[i][2], af[i][3]);
            }
            #pragma unroll
            for (int jj = 0; jj < 2; jj++) {
                int row = wn*32 + jj*16 + (lane & 7) + (((lane >> 4) & 1) << 3);
                int c16 = ks*2 + ((lane >> 3) & 1);
                uint32_t off = SWZ((uint32_t)(row * 128 + c16 * 16));
                uint32_t t0, t1, t2, t3;
                ldsm_x4(Bhs + off, t0, t1, t2, t3);
                bhi[jj*2][0] = t0; bhi[jj*2][1] = t1;
                bhi[jj*2+1][0] = t2; bhi[jj*2+1][1] = t3;
                ldsm_x4(Bls + off, t0, t1, t2, t3);
                blo[jj*2][0] = t0; blo[jj*2][1] = t1;
                blo[jj*2+1][0] = t2; blo[jj*2+1][1] = t3;
            }
            #pragma unroll
            for (int i = 0; i < 4; i++)
                #pragma unroll
                for (int j = 0; j < 4; j++)
                    mma16816(acc[i][j], af[i], bhi[j]);
            #pragma unroll
            for (int i = 0; i < 4; i++)
                #pragma unroll
                for (int j = 0; j < 4; j++)
                    mma16816(acc[i][j], af[i], blo[j]);
        }
    }

    // ---- epilogue ----
    int mrow = bm + wm*64;
    int ncol = bn + wn*32;
    #pragma unroll
    for (int i = 0; i < 4; i++) {
        #pragma unroll
        for (int j = 0; j < 4; j++) {
            int rg = mrow + i*16 + (lane >> 2);
            int cg = ncol + j*8 + 2*(lane & 3);
            float b0v = bias[cg], b1v = bias[cg + 1];
            float v0 = acc[i][j][0] + b0v, v1 = acc[i][j][1] + b1v;
            float v2 = acc[i][j][2] + b0v, v3 = acc[i][j][3] + b1v;
            size_t a0 = (size_t)rg * N + cg;
            size_t a1 = (size_t)(rg + 8) * N + cg;
            if (EPI == 1) {
                float2 q0 = *(const float2*)(res + a0);
                float2 q1 = *(const float2*)(res + a1);
                v0 += q0.x; v1 += q0.y; v2 += q1.x; v3 += q1.y;
                *(float2*)(C + a0) = make_float2(v0, v1);
                *(float2*)(C + a1) = make_float2(v2, v3);
            }
            if (EPI == 2) {
                v0 = 0.5f * v0 * (1.0f + erff(v0 * 0.70710678118654752f));
                v1 = 0.5f * v1 * (1.0f + erff(v1 * 0.70710678118654752f));
                v2 = 0.5f * v2 * (1.0f + erff(v2 * 0.70710678118654752f));
                v3 = 0.5f * v3 * (1.0f + erff(v3 * 0.70710678118654752f));
                *(uint32_t*)(Co + a0) = pack2h(v0, v1);
                *(uint32_t*)(Co + a1) = pack2h(v2, v3);
            }
            if (EPI == 3) {
                float sc = (cg < EMBED) ? QSCALE : 1.0f;
                v0 *= sc; v1 *= sc; v2 *= sc; v3 *= sc;
                uint32_t ph, pl;
                split2h(v0, v1, ph, pl);
                *(uint32_t*)(Chi + a0) = ph;
                *(uint32_t*)(Clo + a0) = pl;
                split2h(v2, v3, ph, pl);
                *(uint32_t*)(Chi + a1) = ph;
                *(uint32_t*)(Clo + a1) = pl;
            }
        }
    }
}

// ================= Flash attention (HMMA fp16 2-product, causal, exp2) =================
// CTA: 128 q rows, 64-key tiles. 8 warps x 16 rows.
// smem: Q 16K | 2 stages x {Khi,Klo,Vhi,Vlo} 8K each = 64K. Total 80K.
#define FA_Q 0u
#define FA_ST 16384u
#define FA_STB 32768u
#define KF(arr, j) (&(arr)[(((j) >> 1) << 2) + (((j) & 1) << 1)])

__global__ void __launch_bounds__(256) fattn_kernel(
    const __half* __restrict__ qkv_hi,
    const __half* __restrict__ qkv_lo,
    __half* __restrict__ att)
{
    extern __shared__ char sm_[];
    uint32_t sb = smem_u32(sm_);
    int tid = threadIdx.x, lane = tid & 31, w = tid >> 5;
    int qblk = blockIdx.x, h = blockIdx.y, b = blockIdx.z;
    int q0 = qblk * 128;
    int ntiles = 2 * (qblk + 1);

    int cc = tid & 7, rr = tid >> 3;   // chunk 0..7, row 0..31
    const char* base_h = (const char*)qkv_hi + ((size_t)(b*SEQ)*3072 + h*64 + cc*8) * 2;
    const char* base_l = (const char*)qkv_lo + ((size_t)(b*SEQ)*3072 + h*64 + cc*8) * 2;

    // ---- Q load (hi only) ----
    #pragma unroll
    for (int i = 0; i < 4; i++) {
        int r = rr + 32*i;
        size_t go = (size_t)(q0 + r) * 6144;
        uint32_t d = SWZ((uint32_t)(r * 128 + cc * 16));
        CP16(sb + FA_Q + d, base_h + go);
    }
    CP_COMMIT();

    // ---- prefetch K/V tile 0 ----
    {
        uint32_t st = sb + FA_ST;
        #pragma unroll
        for (int i = 0; i < 2; i++) {
            int r = rr + 32*i;
            size_t go = (size_t)r * 6144;
            uint32_t d = SWZ((uint32_t)(r * 128 + cc * 16));
            CP16(st + 0     + d, base_h + go + 2048);   // K hi
            CP16(st + 8192  + d, base_l + go + 2048);   // K lo
            CP16(st + 16384 + d, base_h + go + 4096);   // V hi
            CP16(st + 24576 + d, base_l + go + 4096);   // V lo
        }
        CP_COMMIT();
    }

    asm volatile("cp.async.wait_group 1;" ::: "memory");  // Q done
    __syncthreads();

    // ---- Q fragments ----
    uint32_t qf[4][4];
    #pragma unroll
    for (int ks = 0; ks < 4; ks++) {
        int row = w*16 + (lane & 15);
        int c16 = ks*2 + (lane >> 4);
        uint32_t off = SWZ((uint32_t)(row * 128 + c16 * 16));
        ldsm_x4(sb + FA_Q + off, qf[ks][0], qf[ks][1], qf[ks][2], qf[ks][3]);
    }

    float o[8][4];
    #pragma unroll
    for (int j = 0; j < 8; j++)
        #pragma unroll
        for (int q = 0; q < 4; q++) o[j][q] = 0.f;
    float m0 = -INFINITY, m1 = -INFINITY, l0 = 0.f, l1 = 0.f;
    int qg0 = q0 + w*16 + (lane >> 2);
    int qg1 = qg0 + 8;
    int wmin = q0 + w*16, wmax = wmin + 15;

    for (int kt = 0; kt < ntiles; kt++) {
        int k0 = kt * 64;
        if (kt + 1 < ntiles) {
            uint32_t st = sb + FA_ST + (uint32_t)((kt + 1) & 1) * FA_STB;
            #pragma unroll
            for (int i = 0; i < 2; i++) {
                int r = rr + 32*i;
                size_t go = (size_t)((kt + 1) * 64 + r) * 6144;
                uint32_t d = SWZ((uint32_t)(r * 128 + cc * 16));
                CP16(st + 0     + d, base_h + go + 2048);
                CP16(st + 8192  + d, base_l + go + 2048);
                CP16(st + 16384 + d, base_h + go + 4096);
                CP16(st + 24576 + d, base_l + go + 4096);
            }
            CP_COMMIT();
            asm volatile("cp.async.wait_group 1;" ::: "memory");
        } else {
            asm volatile("cp.async.wait_group 0;" ::: "memory");
        }
        __syncthreads();

        if (k0 <= wmax) {
            uint32_t st = sb + FA_ST + (uint32_t)(kt & 1) * FA_STB;

            // ---- S = Q @ K^T (2-product) ----
            float s[8][4];
            #pragma unroll
            for (int j = 0; j < 8; j++)
                #pragma unroll
                for (int q = 0; q < 4; q++) s[j][q] = 0.f;

            #pragma unroll
            for (int ks = 0; ks < 4; ks++) {
                uint32_t kh[16], kl[16];
                #pragma unroll
                for (int jj = 0; jj < 4; jj++) {
                    int row = jj*16 + (lane & 7) + (((lane >> 4) & 1) << 3);
                    int c16 = ks*2 + ((lane >> 3) & 1);
                    uint32_t off = SWZ((uint32_t)(row * 128 + c16 * 16));
                    ldsm_x4(st + off,        kh[jj*4], kh[jj*4+1], kh[jj*4+2], kh[jj*4+3]);
                    ldsm_x4(st + 8192 + off, kl[jj*4], kl[jj*4+1], kl[jj*4+2], kl[jj*4+3]);
                }
                #pragma unroll
                for (int j = 0; j < 8; j++) mma16816(s[j], qf[ks], KF(kh, j));
                #pragma unroll
                for (int j = 0; j < 8; j++) mma16816(s[j], qf[ks], KF(kl, j));
            }

            // ---- causal mask ----
            if (k0 + 63 > wmin) {
                int cb = k0 + 2*(lane & 3);
                #pragma unroll
                for (int j = 0; j < 8; j++) {
                    int c0 = cb + j*8, c1 = c0 + 1;
                    if (c0 > qg0) s[j][0] = -INFINITY;
                    if (c1 > qg0) s[j][1] = -INFINITY;
                    if (c0 > qg1) s[j][2] = -INFINITY;
                    if (c1 > qg1) s[j][3] = -INFINITY;
                }
            }

            // ---- online softmax (base-2) ----
            float tm0 = s[0][0], tm1 = s[0][2];
            #pragma unroll
            for (int j = 0; j < 8; j++) {
                tm0 = fmaxf(tm0, fmaxf(s[j][0], s[j][1]));
                tm1 = fmaxf(tm1, fmaxf(s[j][2], s[j][3]));
            }
            tm0 = fmaxf(tm0, __shfl_xor_sync(0xffffffffu, tm0, 1));
            tm0 = fmaxf(tm0, __shfl_xor_sync(0xffffffffu, tm0, 2));
            tm1 = fmaxf(tm1, __shfl_xor_sync(0xffffffffu, tm1, 1));
            tm1 = fmaxf(tm1, __shfl_xor_sync(0xffffffffu, tm1, 2));

            float nm0 = fmaxf(m0, tm0), nm1 = fmaxf(m1, tm1);
            float a0 = ex2f(m0 - nm0), a1 = ex2f(m1 - nm1);
            m0 = nm0; m1 = nm1;

            float sum0 = 0.f, sum1 = 0.f;
            #pragma unroll
            for (int j = 0; j < 8; j++) {
                s[j][0] = ex2f(s[j][0] - nm0); sum0 += s[j][0];
                s[j][1] = ex2f(s[j][1] - nm0); sum0 += s[j][1];
                s[j][2] = ex2f(s[j][2] - nm1); sum1 += s[j][2];
                s[j][3] = ex2f(s[j][3] - nm1); sum1 += s[j][3];
            }
            sum0 += __shfl_xor_sync(0xffffffffu, sum0, 1);
            sum0 += __shfl_xor_sync(0xffffffffu, sum0, 2);
            sum1 += __shfl_xor_sync(0xffffffffu, sum1, 1);
            sum1 += __shfl_xor_sync(0xffffffffu, sum1, 2);
            l0 = l0 * a0 + sum0;
            l1 = l1 * a1 + sum1;

            #pragma unroll
            for (int j = 0; j < 8; j++) {
                o[j][0] *= a0; o[j][1] *= a0;
                o[j][2] *= a1; o[j][3] *= a1;
            }

            // ---- P fragments (fp16 single) ----
            uint32_t pf[4][4];
            #pragma unroll
            for (int ks = 0; ks < 4; ks++) {
                pf[ks][0] = pack2h(s[2*ks][0],   s[2*ks][1]);
                pf[ks][1] = pack2h(s[2*ks][2],   s[2*ks][3]);
                pf[ks][2] = pack2h(s[2*ks+1][0], s[2*ks+1][1]);
                pf[ks][3] = pack2h(s[2*ks+1][2], s[2*ks+1][3]);
            }

            // ---- O += P @ V (2-product) ----
            #pragma unroll
            for (int ks = 0; ks < 4; ks++) {
                uint32_t vh[16], vl[16];
                #pragma unroll
                for (int nn = 0; nn < 4; nn++) {
                    int key = ks*16 + (lane & 7) + (((lane >> 3) & 1) << 3);
                    int dim = nn*16 + ((lane >> 4) << 3);
                    uint32_t off = SWZ((uint32_t)(key * 128 + dim * 2));
                    ldsm_x4_t(st + 16384 + off, vh[nn*4], vh[nn*4+1], vh[nn*4+2], vh[nn*4+3]);
                    ldsm_x4_t(st + 24576 + off, vl[nn*4], vl[nn*4+1], vl[nn*4+2], vl[nn*4+3]);
                }
                #pragma unroll
                for (int j = 0; j < 8; j++) mma16816(o[j], pf[ks], KF(vh, j));
                #pragma unroll
                for (int j = 0; j < 8; j++) mma16816(o[j], pf[ks], KF(vl, j));
            }
        }
        __syncthreads();
    }

    // ---- epilogue: O/l -> fp16 ----
    float inv0 = 1.0f / l0, inv1 = 1.0f / l1;
    size_t t0 = (size_t)(b*SEQ + qg0) * EMBED + h*64;
    size_t t1 = t0 + (size_t)8 * EMBED;
    #pragma unroll
    for (int j = 0; j < 8; j++) {
        int dd = j*8 + 2*(lane & 3);
        *(uint32_t*)(att + t0 + dd) = pack2h(o[j][0]*inv0, o[j][1]*inv0);
        *(uint32_t*)(att + t1 + dd) = pack2h(o[j][2]*inv1, o[j][3]*inv1);
    }
}

// ================= launch =================
extern "C" void kernel_launch(void* const* d_in, const int* in_sizes, int n_in,
                              void* d_out, int out_size)
{
    const float* x      = (const float*)d_in[0];
    const float* ln1_w  = (const float*)d_in[1];
    const float* ln1_b  = (const float*)d_in[2];
    const float* qkv_w  = (const float*)d_in[3];
    const float* qkv_b  = (const float*)d_in[4];
    const float* proj_w = (const float*)d_in[5];
    const float* proj_b = (const float*)d_in[6];
    const float* ln2_w  = (const float*)d_in[7];
    const float* ln2_b  = (const float*)d_in[8];
    const float* fc1_w  = (const float*)d_in[9];
    const float* fc1_b  = (const float*)d_in[10];
    const float* fc2_w  = (const float*)d_in[11];
    const float* fc2_b  = (const float*)d_in[12];
    float* out = (float*)d_out;

    float *x1;
    __half *xn, *qkv_hi, *qkv_lo, *att, *hbuf;
    __half *qw_hi, *qw_lo, *pw_hi, *pw_lo, *f1_hi, *f1_lo, *f2_hi, *f2_lo;
    cudaGetSymbolAddress((void**)&x1,     g_x1);
    cudaGetSymbolAddress((void**)&xn,     g_xn);
    cudaGetSymbolAddress((void**)&qkv_hi, g_qkv_hi);
    cudaGetSymbolAddress((void**)&qkv_lo, g_qkv_lo);
    cudaGetSymbolAddress((void**)&att,    g_att);
    cudaGetSymbolAddress((void**)&hbuf,   g_h);
    cudaGetSymbolAddress((void**)&qw_hi,  g_qkvw_hi);
    cudaGetSymbolAddress((void**)&qw_lo,  g_qkvw_lo);
    cudaGetSymbolAddress((void**)&pw_hi,  g_projw_hi);
    cudaGetSymbolAddress((void**)&pw_lo,  g_projw_lo);
    cudaGetSymbolAddress((void**)&f1_hi,  g_fc1w_hi);
    cudaGetSymbolAddress((void**)&f1_lo,  g_fc1w_lo);
    cudaGetSymbolAddress((void**)&f2_hi,  g_fc2w_hi);
    cudaGetSymbolAddress((void**)&f2_lo,  g_fc2w_lo);

    int gemm_smem = 3 * STG;   // 147456
    cudaFuncSetAttribute(mm_kernel<1>, cudaFuncAttributeMaxDynamicSharedMemorySize, gemm_smem);
    cudaFuncSetAttribute(mm_kernel<2>, cudaFuncAttributeMaxDynamicSharedMemorySize, gemm_smem);
    cudaFuncSetAttribute(mm_kernel<3>, cudaFuncAttributeMaxDynamicSharedMemorySize, gemm_smem);
    int attn_smem = 16384 + 2 * 32768;   // 81920
    cudaFuncSetAttribute(fattn_kernel, cudaFuncAttributeMaxDynamicSharedMemorySize, attn_smem);

    // weight conversion
    cvt_kernel<<<(3*EMBED*EMBED/4 + 255)/256, 256>>>(qkv_w,  qw_hi, qw_lo, 3*EMBED*EMBED/4);
    cvt_kernel<<<(EMBED*EMBED/4   + 255)/256, 256>>>(proj_w, pw_hi, pw_lo, EMBED*EMBED/4);
    cvt_kernel<<<(HIDDEN*EMBED/4  + 255)/256, 256>>>(fc1_w,  f1_hi, f1_lo, HIDDEN*EMBED/4);
    cvt_kernel<<<(EMBED*HIDDEN/4  + 255)/256, 256>>>(fc2_w,  f2_hi, f2_lo, EMBED*HIDDEN/4);

    // 1. LN1 -> xn (fp16)
    ln_kernel<<<NTOK, 256>>>(x, ln1_w, ln1_b, xn);
    // 2. qkv = xn @ qkv_w^T + qkv_b  (q pre-scaled, fp16 hi/lo)
    mm_kernel<3><<<dim3(NTOK/128, 3*EMBED/128), 256, gemm_smem>>>(
        xn, qw_hi, qw_lo, qkv_b, nullptr, nullptr, nullptr, qkv_hi, qkv_lo,
        NTOK, 3*EMBED, EMBED);
    // 3. attention -> att (fp16)
    fattn_kernel<<<dim3(SEQ/128, HEADS, BATCH), 256, attn_smem>>>(qkv_hi, qkv_lo, att);
    // 4. x1 = att @ proj_w^T + proj_b + x  (fp32)
    mm_kernel<1><<<dim3(NTOK/128, EMBED/128), 256, gemm_smem>>>(
        att, pw_hi, pw_lo, proj_b, x, x1, nullptr, nullptr, nullptr,
        NTOK, EMBED, EMBED);
    // 5. LN2 -> xn (fp16)
    ln_kernel<<<NTOK, 256>>>(x1, ln2_w, ln2_b, xn);
    // 6. h = gelu(xn @ fc1_w^T + fc1_b) -> fp16
    mm_kernel<2><<<dim3(NTOK/128, HIDDEN/128), 256, gemm_smem>>>(
        xn, f1_hi, f1_lo, fc1_b, nullptr, nullptr, hbuf, nullptr, nullptr,
        NTOK, HIDDEN, EMBED);
    // 7. out = h @ fc2_w^T + fc2_b + x1  (fp32)
    mm_kernel<1><<<dim3(NTOK/128, EMBED/128), 256, gemm_smem>>>(
        hbuf, f2_hi, f2_lo, fc2_b, x1, out, nullptr, nullptr, nullptr,
        NTOK, EMBED, HIDDEN);
}

// round 6
// speedup vs baseline: 1.6573x; 1.6573x over previous
#include <cuda_runtime.h>
#include <cuda_fp16.h>
#include <math.h>
#include <stdint.h>

#define EMBED 1024
#define HEADS 16
#define HEAD_DIM 64
#define HIDDEN 4096
#define BATCH 2
#define SEQ 2048
#define NTOK (BATCH*SEQ)   // 4096
#define EPS 1e-6f
#define QSCALE 0.1803368801111204f   // 1/sqrt(64) * log2(e)

// ================= scratch (device globals; no allocation) =================
__device__ __align__(1024) float g_x1  [NTOK * EMBED];

__device__ __align__(1024) __half g_xn  [NTOK * EMBED];        // LN outputs (fp16)
__device__ __align__(1024) __half g_qkv_hi[NTOK * 3 * EMBED];
__device__ __align__(1024) __half g_qkv_lo[NTOK * 3 * EMBED];
__device__ __align__(1024) __half g_att [NTOK * EMBED];
__device__ __align__(1024) __half g_h   [NTOK * HIDDEN];

__device__ __align__(1024) __half g_qkvw_hi [3*EMBED*EMBED];
__device__ __align__(1024) __half g_qkvw_lo [3*EMBED*EMBED];
__device__ __align__(1024) __half g_projw_hi[EMBED*EMBED];
__device__ __align__(1024) __half g_projw_lo[EMBED*EMBED];
__device__ __align__(1024) __half g_fc1w_hi [HIDDEN*EMBED];
__device__ __align__(1024) __half g_fc1w_lo [HIDDEN*EMBED];
__device__ __align__(1024) __half g_fc2w_hi [EMBED*HIDDEN];
__device__ __align__(1024) __half g_fc2w_lo [EMBED*HIDDEN];

// ================= helpers =================
__device__ __forceinline__ uint32_t smem_u32(const void* p) {
    uint32_t a;
    asm("{ .reg .u64 t; cvta.to.shared.u64 t, %1; cvt.u32.u64 %0, t; }" : "=r"(a) : "l"(p));
    return a;
}
#define CP16(dst, src) \
    asm volatile("cp.async.cg.shared.global [%0], [%1], 16;" :: "r"(dst), "l"(src) : "memory")
#define CP_COMMIT() asm volatile("cp.async.commit_group;" ::: "memory")

#define SWZ(x) ((x) ^ (((x) >> 3) & 0x70))

__device__ __forceinline__ void ldsm_x4(uint32_t addr, uint32_t& r0, uint32_t& r1,
                                        uint32_t& r2, uint32_t& r3) {
    asm volatile("ldmatrix.sync.aligned.m8n8.x4.shared.b16 {%0,%1,%2,%3}, [%4];"
                 : "=r"(r0), "=r"(r1), "=r"(r2), "=r"(r3) : "r"(addr));
}
__device__ __forceinline__ void ldsm_x4_t(uint32_t addr, uint32_t& r0, uint32_t& r1,
                                          uint32_t& r2, uint32_t& r3) {
    asm volatile("ldmatrix.sync.aligned.m8n8.x4.trans.shared.b16 {%0,%1,%2,%3}, [%4];"
                 : "=r"(r0), "=r"(r1), "=r"(r2), "=r"(r3) : "r"(addr));
}
__device__ __forceinline__ void mma16816(float* d, const uint32_t* a, const uint32_t* b) {
    asm volatile("mma.sync.aligned.m16n8k16.row.col.f32.f16.f16.f32 "
        "{%0,%1,%2,%3}, {%4,%5,%6,%7}, {%8,%9}, {%0,%1,%2,%3};"
        : "+f"(d[0]), "+f"(d[1]), "+f"(d[2]), "+f"(d[3])
        : "r"(a[0]), "r"(a[1]), "r"(a[2]), "r"(a[3]), "r"(b[0]), "r"(b[1]));
}
__device__ __forceinline__ float ex2f(float x) {
    float y; asm("ex2.approx.f32 %0, %1;" : "=f"(y) : "f"(x)); return y;
}

__device__ __forceinline__ uint32_t pack2h(float a, float b) {
    __half2 t = __floats2half2_rn(a, b);
    return *(uint32_t*)&t;
}
__device__ __forceinline__ void split2h(float x, float y, uint32_t& ph, uint32_t& pl) {
    __half hx = __float2half_rn(x), hy = __float2half_rn(y);
    __half2 hh = __halves2half2(hx, hy);
    ph = *(uint32_t*)&hh;
    pl = pack2h(x - __half2float(hx), y - __half2float(hy));
}

// ================= weight fp32 -> fp16 hi/lo =================
__global__ void __launch_bounds__(256) cvt_kernel(const float* __restrict__ in,
                                                  __half* __restrict__ hi,
                                                  __half* __restrict__ lo,
                                                  int n4)
{
    int i = blockIdx.x * 256 + threadIdx.x;
    if (i >= n4) return;
    float4 v = ((const float4*)in)[i];
    uint2 ph, pl;
    split2h(v.x, v.y, ph.x, pl.x);
    split2h(v.z, v.w, ph.y, pl.y);
    ((uint2*)hi)[i] = ph;
    ((uint2*)lo)[i] = pl;
}

// ================= LayerNorm -> fp16 =================
__global__ void __launch_bounds__(256) ln_kernel(const float* __restrict__ in,
                                                 const float* __restrict__ w,
                                                 const float* __restrict__ b,
                                                 __half* __restrict__ outp)
{
    __shared__ float red[8];
    __shared__ float s_mu, s_rs;
    int row = blockIdx.x;
    int tid = threadIdx.x;
    const float4* ip = (const float4*)(in + (size_t)row * EMBED);
    float4 v = ip[tid];

    float s = v.x + v.y + v.z + v.w;
    #pragma unroll
    for (int o = 16; o; o >>= 1) s += __shfl_xor_sync(0xffffffffu, s, o);
    if ((tid & 31) == 0) red[tid >> 5] = s;
    __syncthreads();
    if (tid == 0) {
        float tot = 0.f;
        #pragma unroll
        for (int i = 0; i < 8; i++) tot += red[i];
        s_mu = tot * (1.0f / EMBED);
    }
    __syncthreads();
    float mu = s_mu;

    float dx = v.x - mu, dy = v.y - mu, dz = v.z - mu, dw = v.w - mu;
    float s2 = dx*dx + dy*dy + dz*dz + dw*dw;
    #pragma unroll
    for (int o = 16; o; o >>= 1) s2 += __shfl_xor_sync(0xffffffffu, s2, o);
    __syncthreads();
    if ((tid & 31) == 0) red[tid >> 5] = s2;
    __syncthreads();
    if (tid == 0) {
        float tot = 0.f;
        #pragma unroll
        for (int i = 0; i < 8; i++) tot += red[i];
        s_rs = rsqrtf(tot * (1.0f / EMBED) + EPS);
    }
    __syncthreads();
    float rs = s_rs;

    float4 wv = ((const float4*)w)[tid];
    float4 bv = ((const float4*)b)[tid];
    uint2 o4;
    o4.x = pack2h(dx * rs * wv.x + bv.x, dy * rs * wv.y + bv.y);
    o4.y = pack2h(dz * rs * wv.z + bv.z, dw * rs * wv.w + bv.w);
    ((uint2*)(outp + (size_t)row * EMBED))[tid] = o4;
}

// ================= HMMA GEMM (NT, fp16 2-product, fp32 accum) =================
// C[m,n] = sum_k A[m,k]*(Bhi+Blo)[n,k] + bias[n]
// EPI: 1 = bias + residual (fp32), 2 = bias + gelu (fp16), 3 = bias + qscale (fp16 hi/lo)
// 2-stage pipeline, 48KB/stage -> 96KB/CTA -> 2 CTAs/SM.
#define T16K 16384
#define STG 49152     // 3 tiles * 16KB

template<int EPI>
__global__ void __launch_bounds__(256, 2) mm_kernel(
    const __half* __restrict__ A,
    const __half* __restrict__ Bhi, const __half* __restrict__ Blo,
    const float* __restrict__ bias, const float* __restrict__ res,
    float* __restrict__ C, __half* __restrict__ Co,
    __half* __restrict__ Chi, __half* __restrict__ Clo,
    int M, int N, int K)
{
    extern __shared__ char smem[];   // 2 stages * 48KB = 96KB
    uint32_t sb = smem_u32(smem);
    int tid = threadIdx.x;
    int bm = blockIdx.x * 128;
    int bn = blockIdx.y * 128;
    int lane = tid & 31, w = tid >> 5;
    int wm = w & 1, wn = w >> 1;     // warp grid 2(m) x 4(n)

    int cc = tid & 7;
    int r0 = tid >> 3;
    const char* pA  = (const char*)(A   + (size_t)(bm + r0) * K) + cc * 16;
    const char* pBh = (const char*)(Bhi + (size_t)(bn + r0) * K) + cc * 16;
    const char* pBl = (const char*)(Blo + (size_t)(bn + r0) * K) + cc * 16;
    size_t rowblk = (size_t)K * 64;  // 32 rows * K * 2B
    uint32_t d0[4];
    #pragma unroll
    for (int j = 0; j < 4; j++) d0[j] = SWZ((uint32_t)((r0 + 32*j) * 128 + cc * 16));

    float acc[4][4][4];
    #pragma unroll
    for (int i = 0; i < 4; i++)
        #pragma unroll
        for (int j = 0; j < 4; j++)
            #pragma unroll
            for (int q = 0; q < 4; q++) acc[i][j][q] = 0.f;

    int nCh = K >> 6;

    // prologue: prefetch chunk 0
    {
        uint32_t st = sb;
        #pragma unroll
        for (int j = 0; j < 4; j++) {
            size_t so = (size_t)j * rowblk;
            CP16(st + 0*T16K + d0[j], pA  + so);
            CP16(st + 1*T16K + d0[j], pBh + so);
            CP16(st + 2*T16K + d0[j], pBl + so);
        }
        CP_COMMIT();
    }

    for (int c = 0; c < nCh; c++) {
        // R4 ordering: issue prefetch for next chunk FIRST, then wait, then compute
        if (c + 1 < nCh) {
            uint32_t st = sb + (uint32_t)((c + 1) & 1) * STG;
            size_t koff = (size_t)(c + 1) * 128;
            #pragma unroll
            for (int j = 0; j < 4; j++) {
                size_t so = (size_t)j * rowblk + koff;
                CP16(st + 0*T16K + d0[j], pA  + so);
                CP16(st + 1*T16K + d0[j], pBh + so);
                CP16(st + 2*T16K + d0[j], pBl + so);
            }
            CP_COMMIT();
            asm volatile("cp.async.wait_group 1;" ::: "memory");
        } else {
            asm volatile("cp.async.wait_group 0;" ::: "memory");
        }
        __syncthreads();

        uint32_t st = sb + (uint32_t)(c & 1) * STG;
        uint32_t As = st, Bhs = st + T16K, Bls = st + 2*T16K;

        #pragma unroll
        for (int ks = 0; ks < 4; ks++) {
            uint32_t af[4][4], bhi[4][2], blo[4][2];
            #pragma unroll
            for (int i = 0; i < 4; i++) {
                int row = wm*64 + i*16 + (lane & 15);
                int c16 = ks*2 + (lane >> 4);
                uint32_t off = SWZ((uint32_t)(row * 128 + c16 * 16));
                ldsm_x4(As + off, af[i][0], af[i][1], af[i][2], af[i][3]);
            }
            #pragma unroll
            for (int jj = 0; jj < 2; jj++) {
                int row = wn*32 + jj*16 + (lane & 7) + (((lane >> 4) & 1) << 3);
                int c16 = ks*2 + ((lane >> 3) & 1);
                uint32_t off = SWZ((uint32_t)(row * 128 + c16 * 16));
                uint32_t t0, t1, t2, t3;
                ldsm_x4(Bhs + off, t0, t1, t2, t3);
                bhi[jj*2][0] = t0; bhi[jj*2][1] = t1;
                bhi[jj*2+1][0] = t2; bhi[jj*2+1][1] = t3;
                ldsm_x4(Bls + off, t0, t1, t2, t3);
                blo[jj*2][0] = t0; blo[jj*2][1] = t1;
                blo[jj*2+1][0] = t2; blo[jj*2+1][1] = t3;
            }
            #pragma unroll
            for (int i = 0; i < 4; i++)
                #pragma unroll
                for (int j = 0; j < 4; j++)
                    mma16816(acc[i][j], af[i], bhi[j]);
            #pragma unroll
            for (int i = 0; i < 4; i++)
                #pragma unroll
                for (int j = 0; j < 4; j++)
                    mma16816(acc[i][j], af[i], blo[j]);
        }
        __syncthreads();
    }

    // ---- epilogue ----
    int mrow = bm + wm*64;
    int ncol = bn + wn*32;
    #pragma unroll
    for (int i = 0; i < 4; i++) {
        #pragma unroll
        for (int j = 0; j < 4; j++) {
            int rg = mrow + i*16 + (lane >> 2);
            int cg = ncol + j*8 + 2*(lane & 3);
            float b0v = bias[cg], b1v = bias[cg + 1];
            float v0 = acc[i][j][0] + b0v, v1 = acc[i][j][1] + b1v;
            float v2 = acc[i][j][2] + b0v, v3 = acc[i][j][3] + b1v;
            size_t a0 = (size_t)rg * N + cg;
            size_t a1 = (size_t)(rg + 8) * N + cg;
            if (EPI == 1) {
                float2 q0 = *(const float2*)(res + a0);
                float2 q1 = *(const float2*)(res + a1);
                v0 += q0.x; v1 += q0.y; v2 += q1.x; v3 += q1.y;
                *(float2*)(C + a0) = make_float2(v0, v1);
                *(float2*)(C + a1) = make_float2(v2, v3);
            }
            if (EPI == 2) {
                v0 = 0.5f * v0 * (1.0f + erff(v0 * 0.70710678118654752f));
                v1 = 0.5f * v1 * (1.0f + erff(v1 * 0.70710678118654752f));
                v2 = 0.5f * v2 * (1.0f + erff(v2 * 0.70710678118654752f));
                v3 = 0.5f * v3 * (1.0f + erff(v3 * 0.70710678118654752f));
                *(uint32_t*)(Co + a0) = pack2h(v0, v1);
                *(uint32_t*)(Co + a1) = pack2h(v2, v3);
            }
            if (EPI == 3) {
                float sc = (cg < EMBED) ? QSCALE : 1.0f;
                v0 *= sc; v1 *= sc; v2 *= sc; v3 *= sc;
                uint32_t ph, pl;
                split2h(v0, v1, ph, pl);
                *(uint32_t*)(Chi + a0) = ph;
                *(uint32_t*)(Clo + a0) = pl;
                split2h(v2, v3, ph, pl);
                *(uint32_t*)(Chi + a1) = ph;
                *(uint32_t*)(Clo + a1) = pl;
            }
        }
    }
}

// ================= Flash attention (HMMA fp16 2-product, causal, exp2) =================
// CTA: 128 q rows, 64-key tiles. 8 warps x 16 rows.
// smem: Q 16K | 2 stages x {Khi,Klo,Vhi,Vlo} 8K each = 64K. Total 80K.
#define FA_Q 0u
#define FA_ST 16384u
#define FA_STB 32768u
#define KF(arr, j) (&(arr)[(((j) >> 1) << 2) + (((j) & 1) << 1)])

__global__ void __launch_bounds__(256) fattn_kernel(
    const __half* __restrict__ qkv_hi,
    const __half* __restrict__ qkv_lo,
    __half* __restrict__ att)
{
    extern __shared__ char sm_[];
    uint32_t sb = smem_u32(sm_);
    int tid = threadIdx.x, lane = tid & 31, w = tid >> 5;
    int qblk = blockIdx.x, h = blockIdx.y, b = blockIdx.z;
    int q0 = qblk * 128;
    int ntiles = 2 * (qblk + 1);

    int cc = tid & 7, rr = tid >> 3;   // chunk 0..7, row 0..31
    const char* base_h = (const char*)qkv_hi + ((size_t)(b*SEQ)*3072 + h*64 + cc*8) * 2;
    const char* base_l = (const char*)qkv_lo + ((size_t)(b*SEQ)*3072 + h*64 + cc*8) * 2;

    // ---- Q load (hi only) ----
    #pragma unroll
    for (int i = 0; i < 4; i++) {
        int r = rr + 32*i;
        size_t go = (size_t)(q0 + r) * 6144;
        uint32_t d = SWZ((uint32_t)(r * 128 + cc * 16));
        CP16(sb + FA_Q + d, base_h + go);
    }
    CP_COMMIT();

    // ---- prefetch K/V tile 0 ----
    {
        uint32_t st = sb + FA_ST;
        #pragma unroll
        for (int i = 0; i < 2; i++) {
            int r = rr + 32*i;
            size_t go = (size_t)r * 6144;
            uint32_t d = SWZ((uint32_t)(r * 128 + cc * 16));
            CP16(st + 0     + d, base_h + go + 2048);   // K hi
            CP16(st + 8192  + d, base_l + go + 2048);   // K lo
            CP16(st + 16384 + d, base_h + go + 4096);   // V hi
            CP16(st + 24576 + d, base_l + go + 4096);   // V lo
        }
        CP_COMMIT();
    }

    asm volatile("cp.async.wait_group 1;" ::: "memory");  // Q done
    __syncthreads();

    // ---- Q fragments ----
    uint32_t qf[4][4];
    #pragma unroll
    for (int ks = 0; ks < 4; ks++) {
        int row = w*16 + (lane & 15);
        int c16 = ks*2 + (lane >> 4);
        uint32_t off = SWZ((uint32_t)(row * 128 + c16 * 16));
        ldsm_x4(sb + FA_Q + off, qf[ks][0], qf[ks][1], qf[ks][2], qf[ks][3]);
    }

    float o[8][4];
    #pragma unroll
    for (int j = 0; j < 8; j++)
        #pragma unroll
        for (int q = 0; q < 4; q++) o[j][q] = 0.f;
    float m0 = -INFINITY, m1 = -INFINITY, l0 = 0.f, l1 = 0.f;
    int qg0 = q0 + w*16 + (lane >> 2);
    int qg1 = qg0 + 8;
    int wmin = q0 + w*16, wmax = wmin + 15;

    for (int kt = 0; kt < ntiles; kt++) {
        int k0 = kt * 64;
        if (kt + 1 < ntiles) {
            uint32_t st = sb + FA_ST + (uint32_t)((kt + 1) & 1) * FA_STB;
            #pragma unroll
            for (int i = 0; i < 2; i++) {
                int r = rr + 32*i;
                size_t go = (size_t)((kt + 1) * 64 + r) * 6144;
                uint32_t d = SWZ((uint32_t)(r * 128 + cc * 16));
                CP16(st + 0     + d, base_h + go + 2048);
                CP16(st + 8192  + d, base_l + go + 2048);
                CP16(st + 16384 + d, base_h + go + 4096);
                CP16(st + 24576 + d, base_l + go + 4096);
            }
            CP_COMMIT();
            asm volatile("cp.async.wait_group 1;" ::: "memory");
        } else {
            asm volatile("cp.async.wait_group 0;" ::: "memory");
        }
        __syncthreads();

        if (k0 <= wmax) {
            uint32_t st = sb + FA_ST + (uint32_t)(kt & 1) * FA_STB;

            // ---- S = Q @ K^T (2-product) ----
            float s[8][4];
            #pragma unroll
            for (int j = 0; j < 8; j++)
                #pragma unroll
                for (int q = 0; q < 4; q++) s[j][q] = 0.f;

            #pragma unroll
            for (int ks = 0; ks < 4; ks++) {
                uint32_t kh[16], kl[16];
                #pragma unroll
                for (int jj = 0; jj < 4; jj++) {
                    int row = jj*16 + (lane & 7) + (((lane >> 4) & 1) << 3);
                    int c16 = ks*2 + ((lane >> 3) & 1);
                    uint32_t off = SWZ((uint32_t)(row * 128 + c16 * 16));
                    ldsm_x4(st + off,        kh[jj*4], kh[jj*4+1], kh[jj*4+2], kh[jj*4+3]);
                    ldsm_x4(st + 8192 + off, kl[jj*4], kl[jj*4+1], kl[jj*4+2], kl[jj*4+3]);
                }
                #pragma unroll
                for (int j = 0; j < 8; j++) mma16816(s[j], qf[ks], KF(kh, j));
                #pragma unroll
                for (int j = 0; j < 8; j++) mma16816(s[j], qf[ks], KF(kl, j));
            }

            // ---- causal mask ----
            if (k0 + 63 > wmin) {
                int cb = k0 + 2*(lane & 3);
                #pragma unroll
                for (int j = 0; j < 8; j++) {
                    int c0 = cb + j*8, c1 = c0 + 1;
                    if (c0 > qg0) s[j][0] = -INFINITY;
                    if (c1 > qg0) s[j][1] = -INFINITY;
                    if (c0 > qg1) s[j][2] = -INFINITY;
                    if (c1 > qg1) s[j][3] = -INFINITY;
                }
            }

            // ---- online softmax (base-2) ----
            float tm0 = s[0][0], tm1 = s[0][2];
            #pragma unroll
            for (int j = 0; j < 8; j++) {
                tm0 = fmaxf(tm0, fmaxf(s[j][0], s[j][1]));
                tm1 = fmaxf(tm1, fmaxf(s[j][2], s[j][3]));
            }
            tm0 = fmaxf(tm0, __shfl_xor_sync(0xffffffffu, tm0, 1));
            tm0 = fmaxf(tm0, __shfl_xor_sync(0xffffffffu, tm0, 2));
            tm1 = fmaxf(tm1, __shfl_xor_sync(0xffffffffu, tm1, 1));
            tm1 = fmaxf(tm1, __shfl_xor_sync(0xffffffffu, tm1, 2));

            float nm0 = fmaxf(m0, tm0), nm1 = fmaxf(m1, tm1);
            float a0 = ex2f(m0 - nm0), a1 = ex2f(m1 - nm1);
            m0 = nm0; m1 = nm1;

            float sum0 = 0.f, sum1 = 0.f;
            #pragma unroll
            for (int j = 0; j < 8; j++) {
                s[j][0] = ex2f(s[j][0] - nm0); sum0 += s[j][0];
                s[j][1] = ex2f(s[j][1] - nm0); sum0 += s[j][1];
                s[j][2] = ex2f(s[j][2] - nm1); sum1 += s[j][2];
                s[j][3] = ex2f(s[j][3] - nm1); sum1 += s[j][3];
            }
            sum0 += __shfl_xor_sync(0xffffffffu, sum0, 1);
            sum0 += __shfl_xor_sync(0xffffffffu, sum0, 2);
            sum1 += __shfl_xor_sync(0xffffffffu, sum1, 1);
            sum1 += __shfl_xor_sync(0xffffffffu, sum1, 2);
            l0 = l0 * a0 + sum0;
            l1 = l1 * a1 + sum1;

            #pragma unroll
            for (int j = 0; j < 8; j++) {
                o[j][0] *= a0; o[j][1] *= a0;
                o[j][2] *= a1; o[j][3] *= a1;
            }

            // ---- P fragments (fp16 single) ----
            uint32_t pf[4][4];
            #pragma unroll
            for (int ks = 0; ks < 4; ks++) {
                pf[ks][0] = pack2h(s[2*ks][0],   s[2*ks][1]);
                pf[ks][1] = pack2h(s[2*ks][2],   s[2*ks][3]);
                pf[ks][2] = pack2h(s[2*ks+1][0], s[2*ks+1][1]);
                pf[ks][3] = pack2h(s[2*ks+1][2], s[2*ks+1][3]);
            }

            // ---- O += P @ V (2-product) ----
            #pragma unroll
            for (int ks = 0; ks < 4; ks++) {
                uint32_t vh[16], vl[16];
                #pragma unroll
                for (int nn = 0; nn < 4; nn++) {
                    int key = ks*16 + (lane & 7) + (((lane >> 3) & 1) << 3);
                    int dim = nn*16 + ((lane >> 4) << 3);
                    uint32_t off = SWZ((uint32_t)(key * 128 + dim * 2));
                    ldsm_x4_t(st + 16384 + off, vh[nn*4], vh[nn*4+1], vh[nn*4+2], vh[nn*4+3]);
                    ldsm_x4_t(st + 24576 + off, vl[nn*4], vl[nn*4+1], vl[nn*4+2], vl[nn*4+3]);
                }
                #pragma unroll
                for (int j = 0; j < 8; j++) mma16816(o[j], pf[ks], KF(vh, j));
                #pragma unroll
                for (int j = 0; j < 8; j++) mma16816(o[j], pf[ks], KF(vl, j));
            }
        }
        __syncthreads();
    }

    // ---- epilogue: O/l -> fp16 ----
    float inv0 = 1.0f / l0, inv1 = 1.0f / l1;
    size_t t0 = (size_t)(b*SEQ + qg0) * EMBED + h*64;
    size_t t1 = t0 + (size_t)8 * EMBED;
    #pragma unroll
    for (int j = 0; j < 8; j++) {
        int dd = j*8 + 2*(lane & 3);
        *(uint32_t*)(att + t0 + dd) = pack2h(o[j][0]*inv0, o[j][1]*inv0);
        *(uint32_t*)(att + t1 + dd) = pack2h(o[j][2]*inv1, o[j][3]*inv1);
    }
}

// ================= launch =================
extern "C" void kernel_launch(void* const* d_in, const int* in_sizes, int n_in,
                              void* d_out, int out_size)
{
    const float* x      = (const float*)d_in[0];
    const float* ln1_w  = (const float*)d_in[1];
    const float* ln1_b  = (const float*)d_in[2];
    const float* qkv_w  = (const float*)d_in[3];
    const float* qkv_b  = (const float*)d_in[4];
    const float* proj_w = (const float*)d_in[5];
    const float* proj_b = (const float*)d_in[6];
    const float* ln2_w  = (const float*)d_in[7];
    const float* ln2_b  = (const float*)d_in[8];
    const float* fc1_w  = (const float*)d_in[9];
    const float* fc1_b  = (const float*)d_in[10];
    const float* fc2_w  = (const float*)d_in[11];
    const float* fc2_b  = (const float*)d_in[12];
    float* out = (float*)d_out;

    float *x1;
    __half *xn, *qkv_hi, *qkv_lo, *att, *hbuf;
    __half *qw_hi, *qw_lo, *pw_hi, *pw_lo, *f1_hi, *f1_lo, *f2_hi, *f2_lo;
    cudaGetSymbolAddress((void**)&x1,     g_x1);
    cudaGetSymbolAddress((void**)&xn,     g_xn);
    cudaGetSymbolAddress((void**)&qkv_hi, g_qkv_hi);
    cudaGetSymbolAddress((void**)&qkv_lo, g_qkv_lo);
    cudaGetSymbolAddress((void**)&att,    g_att);
    cudaGetSymbolAddress((void**)&hbuf,   g_h);
    cudaGetSymbolAddress((void**)&qw_hi,  g_qkvw_hi);
    cudaGetSymbolAddress((void**)&qw_lo,  g_qkvw_lo);
    cudaGetSymbolAddress((void**)&pw_hi,  g_projw_hi);
    cudaGetSymbolAddress((void**)&pw_lo,  g_projw_lo);
    cudaGetSymbolAddress((void**)&f1_hi,  g_fc1w_hi);
    cudaGetSymbolAddress((void**)&f1_lo,  g_fc1w_lo);
    cudaGetSymbolAddress((void**)&f2_hi,  g_fc2w_hi);
    cudaGetSymbolAddress((void**)&f2_lo,  g_fc2w_lo);

    int gemm_smem = 2 * STG;   // 98304 -> 2 CTAs/SM
    cudaFuncSetAttribute(mm_kernel<1>, cudaFuncAttributeMaxDynamicSharedMemorySize, gemm_smem);
    cudaFuncSetAttribute(mm_kernel<2>, cudaFuncAttributeMaxDynamicSharedMemorySize, gemm_smem);
    cudaFuncSetAttribute(mm_kernel<3>, cudaFuncAttributeMaxDynamicSharedMemorySize, gemm_smem);
    int attn_smem = 16384 + 2 * 32768;   // 81920
    cudaFuncSetAttribute(fattn_kernel, cudaFuncAttributeMaxDynamicSharedMemorySize, attn_smem);

    // weight conversion
    cvt_kernel<<<(3*EMBED*EMBED/4 + 255)/256, 256>>>(qkv_w,  qw_hi, qw_lo, 3*EMBED*EMBED/4);
    cvt_kernel<<<(EMBED*EMBED/4   + 255)/256, 256>>>(proj_w, pw_hi, pw_lo, EMBED*EMBED/4);
    cvt_kernel<<<(HIDDEN*EMBED/4  + 255)/256, 256>>>(fc1_w,  f1_hi, f1_lo, HIDDEN*EMBED/4);
    cvt_kernel<<<(EMBED*HIDDEN/4  + 255)/256, 256>>>(fc2_w,  f2_hi, f2_lo, EMBED*HIDDEN/4);

    // 1. LN1 -> xn (fp16)
    ln_kernel<<<NTOK, 256>>>(x, ln1_w, ln1_b, xn);
    // 2. qkv = xn @ qkv_w^T + qkv_b  (q pre-scaled, fp16 hi/lo)
    mm_kernel<3><<<dim3(NTOK/128, 3*EMBED/128), 256, gemm_smem>>>(
        xn, qw_hi, qw_lo, qkv_b, nullptr, nullptr, nullptr, qkv_hi, qkv_lo,
        NTOK, 3*EMBED, EMBED);
    // 3. attention -> att (fp16)
    fattn_kernel<<<dim3(SEQ/128, HEADS, BATCH), 256, attn_smem>>>(qkv_hi, qkv_lo, att);
    // 4. x1 = att @ proj_w^T + proj_b + x  (fp32)
    mm_kernel<1><<<dim3(NTOK/128, EMBED/128), 256, gemm_smem>>>(
        att, pw_hi, pw_lo, proj_b, x, x1, nullptr, nullptr, nullptr,
        NTOK, EMBED, EMBED);
    // 5. LN2 -> xn (fp16)
    ln_kernel<<<NTOK, 256>>>(x1, ln2_w, ln2_b, xn);
    // 6. h = gelu(xn @ fc1_w^T + fc1_b) -> fp16
    mm_kernel<2><<<dim3(NTOK/128, HIDDEN/128), 256, gemm_smem>>>(
        xn, f1_hi, f1_lo, fc1_b, nullptr, nullptr, hbuf, nullptr, nullptr,
        NTOK, HIDDEN, EMBED);
    // 7. out = h @ fc2_w^T + fc2_b + x1  (fp32)
    mm_kernel<1><<<dim3(NTOK/128, EMBED/128), 256, gemm_smem>>>(
        hbuf, f2_hi, f2_lo, fc2_b, x1, out, nullptr, nullptr, nullptr,
        NTOK, EMBED, HIDDEN);
}

// round 7
// speedup vs baseline: 2.7191x; 1.6407x over previous
#include <cuda_runtime.h>
#include <cuda_fp16.h>
#include <math.h>
#include <stdint.h>

#define EMBED 1024
#define HEADS 16
#define HEAD_DIM 64
#define HIDDEN 4096
#define BATCH 2
#define SEQ 2048
#define NTOK (BATCH*SEQ)   // 4096
#define EPS 1e-6f
#define QSCALE 0.1803368801111204f   // 1/sqrt(64) * log2(e)

// ================= scratch (device globals; no allocation) =================
__device__ __align__(1024) float g_x1  [NTOK * EMBED];

__device__ __align__(1024) __half g_xn  [NTOK * EMBED];
__device__ __align__(1024) __half g_qkv [NTOK * 3 * EMBED];
__device__ __align__(1024) __half g_att [NTOK * EMBED];
__device__ __align__(1024) __half g_h   [NTOK * HIDDEN];

__device__ __align__(1024) __half g_qkvw [3*EMBED*EMBED];
__device__ __align__(1024) __half g_projw[EMBED*EMBED];
__device__ __align__(1024) __half g_fc1w [HIDDEN*EMBED];
__device__ __align__(1024) __half g_fc2w [EMBED*HIDDEN];

// ================= helpers =================
__device__ __forceinline__ uint32_t smem_u32(const void* p) {
    uint32_t a;
    asm("{ .reg .u64 t; cvta.to.shared.u64 t, %1; cvt.u32.u64 %0, t; }" : "=r"(a) : "l"(p));
    return a;
}
#define CP16(dst, src) \
    asm volatile("cp.async.cg.shared.global [%0], [%1], 16;" :: "r"(dst), "l"(src) : "memory")
#define CP_COMMIT() asm volatile("cp.async.commit_group;" ::: "memory")

#define SWZ(x) ((x) ^ (((x) >> 3) & 0x70))

__device__ __forceinline__ void ldsm_x4(uint32_t addr, uint32_t& r0, uint32_t& r1,
                                        uint32_t& r2, uint32_t& r3) {
    asm volatile("ldmatrix.sync.aligned.m8n8.x4.shared.b16 {%0,%1,%2,%3}, [%4];"
                 : "=r"(r0), "=r"(r1), "=r"(r2), "=r"(r3) : "r"(addr));
}
__device__ __forceinline__ void ldsm_x4_t(uint32_t addr, uint32_t& r0, uint32_t& r1,
                                          uint32_t& r2, uint32_t& r3) {
    asm volatile("ldmatrix.sync.aligned.m8n8.x4.trans.shared.b16 {%0,%1,%2,%3}, [%4];"
                 : "=r"(r0), "=r"(r1), "=r"(r2), "=r"(r3) : "r"(addr));
}
__device__ __forceinline__ void mma16816(float* d, const uint32_t* a, const uint32_t* b) {
    asm volatile("mma.sync.aligned.m16n8k16.row.col.f32.f16.f16.f32 "
        "{%0,%1,%2,%3}, {%4,%5,%6,%7}, {%8,%9}, {%0,%1,%2,%3};"
        : "+f"(d[0]), "+f"(d[1]), "+f"(d[2]), "+f"(d[3])
        : "r"(a[0]), "r"(a[1]), "r"(a[2]), "r"(a[3]), "r"(b[0]), "r"(b[1]));
}
__device__ __forceinline__ float ex2f(float x) {
    float y; asm("ex2.approx.f32 %0, %1;" : "=f"(y) : "f"(x)); return y;
}
__device__ __forceinline__ uint32_t pack2h(float a, float b) {
    __half2 t = __floats2half2_rn(a, b);
    return *(uint32_t*)&t;
}

// ================= weight fp32 -> fp16 =================
__global__ void __launch_bounds__(256) cvt_kernel(const float* __restrict__ in,
                                                  __half* __restrict__ outp,
                                                  int n4)
{
    int i = blockIdx.x * 256 + threadIdx.x;
    if (i >= n4) return;
    float4 v = ((const float4*)in)[i];
    uint2 o;
    o.x = pack2h(v.x, v.y);
    o.y = pack2h(v.z, v.w);
    ((uint2*)outp)[i] = o;
}

// ================= LayerNorm -> fp16 =================
__global__ void __launch_bounds__(256) ln_kernel(const float* __restrict__ in,
                                                 const float* __restrict__ w,
                                                 const float* __restrict__ b,
                                                 __half* __restrict__ outp)
{
    __shared__ float red[8];
    __shared__ float s_mu, s_rs;
    int row = blockIdx.x;
    int tid = threadIdx.x;
    const float4* ip = (const float4*)(in + (size_t)row * EMBED);
    float4 v = ip[tid];

    float s = v.x + v.y + v.z + v.w;
    #pragma unroll
    for (int o = 16; o; o >>= 1) s += __shfl_xor_sync(0xffffffffu, s, o);
    if ((tid & 31) == 0) red[tid >> 5] = s;
    __syncthreads();
    if (tid == 0) {
        float tot = 0.f;
        #pragma unroll
        for (int i = 0; i < 8; i++) tot += red[i];
        s_mu = tot * (1.0f / EMBED);
    }
    __syncthreads();
    float mu = s_mu;

    float dx = v.x - mu, dy = v.y - mu, dz = v.z - mu, dw = v.w - mu;
    float s2 = dx*dx + dy*dy + dz*dz + dw*dw;
    #pragma unroll
    for (int o = 16; o; o >>= 1) s2 += __shfl_xor_sync(0xffffffffu, s2, o);
    __syncthreads();
    if ((tid & 31) == 0) red[tid >> 5] = s2;
    __syncthreads();
    if (tid == 0) {
        float tot = 0.f;
        #pragma unroll
        for (int i = 0; i < 8; i++) tot += red[i];
        s_rs = rsqrtf(tot * (1.0f / EMBED) + EPS);
    }
    __syncthreads();
    float rs = s_rs;

    float4 wv = ((const float4*)w)[tid];
    float4 bv = ((const float4*)b)[tid];
    uint2 o4;
    o4.x = pack2h(dx * rs * wv.x + bv.x, dy * rs * wv.y + bv.y);
    o4.y = pack2h(dz * rs * wv.z + bv.z, dw * rs * wv.w + bv.w);
    ((uint2*)(outp + (size_t)row * EMBED))[tid] = o4;
}

// ================= HMMA GEMM (NT, fp16, fp32 accum) =================
// C[m,n] = sum_k A[m,k]*B[n,k] + bias[n]
// EPI: 1 = bias + residual (fp32), 2 = bias + gelu (fp16), 3 = bias + qscale (fp16)
// 3-stage pipeline, 32KB/stage -> 96KB/CTA -> 2 CTAs/SM.
#define T16K 16384
#define STG 32768     // 2 tiles * 16KB

template<int EPI>
__global__ void __launch_bounds__(256, 2) mm_kernel(
    const __half* __restrict__ A, const __half* __restrict__ B,
    const float* __restrict__ bias, const float* __restrict__ res,
    float* __restrict__ C, __half* __restrict__ Co,
    int M, int N, int K)
{
    extern __shared__ char smem[];   // 3 stages * 32KB = 96KB
    uint32_t sb = smem_u32(smem);
    int tid = threadIdx.x;
    int bm = blockIdx.x * 128;
    int bn = blockIdx.y * 128;
    int lane = tid & 31, w = tid >> 5;
    int wm = w & 1, wn = w >> 1;     // warp grid 2(m) x 4(n)

    int cc = tid & 7;
    int r0 = tid >> 3;
    const char* pA = (const char*)(A + (size_t)(bm + r0) * K) + cc * 16;
    const char* pB = (const char*)(B + (size_t)(bn + r0) * K) + cc * 16;
    size_t rowblk = (size_t)K * 64;  // 32 rows * K * 2B
    uint32_t d0[4];
    #pragma unroll
    for (int j = 0; j < 4; j++) d0[j] = SWZ((uint32_t)((r0 + 32*j) * 128 + cc * 16));

    float acc[4][4][4];
    #pragma unroll
    for (int i = 0; i < 4; i++)
        #pragma unroll
        for (int j = 0; j < 4; j++)
            #pragma unroll
            for (int q = 0; q < 4; q++) acc[i][j][q] = 0.f;

    int nCh = K >> 6;

    // prologue: prefetch chunks 0 and 1
    #pragma unroll
    for (int pc = 0; pc < 2; pc++) {
        uint32_t st = sb + (uint32_t)pc * STG;
        size_t koff = (size_t)pc * 128;
        #pragma unroll
        for (int j = 0; j < 4; j++) {
            size_t so = (size_t)j * rowblk + koff;
            CP16(st + 0*T16K + d0[j], pA + so);
            CP16(st + 1*T16K + d0[j], pB + so);
        }
        CP_COMMIT();
    }

    for (int c = 0; c < nCh; c++) {
        if (c + 2 < nCh) {
            int sidx = (c + 2) % 3;
            uint32_t st = sb + (uint32_t)sidx * STG;
            size_t koff = (size_t)(c + 2) * 128;
            #pragma unroll
            for (int j = 0; j < 4; j++) {
                size_t so = (size_t)j * rowblk + koff;
                CP16(st + 0*T16K + d0[j], pA + so);
                CP16(st + 1*T16K + d0[j], pB + so);
            }
            CP_COMMIT();
            asm volatile("cp.async.wait_group 2;" ::: "memory");
        } else if (c + 1 < nCh) {
            asm volatile("cp.async.wait_group 1;" ::: "memory");
        } else {
            asm volatile("cp.async.wait_group 0;" ::: "memory");
        }
        __syncthreads();

        uint32_t st = sb + (uint32_t)(c % 3) * STG;
        uint32_t As = st, Bs = st + T16K;

        #pragma unroll
        for (int ks = 0; ks < 4; ks++) {
            uint32_t af[4][4], bf[4][2];
            #pragma unroll
            for (int i = 0; i < 4; i++) {
                int row = wm*64 + i*16 + (lane & 15);
                int c16 = ks*2 + (lane >> 4);
                uint32_t off = SWZ((uint32_t)(row * 128 + c16 * 16));
                ldsm_x4(As + off, af[i][0], af[i][1], af[i][2], af[i][3]);
            }
            #pragma unroll
            for (int jj = 0; jj < 2; jj++) {
                int row = wn*32 + jj*16 + (lane & 7) + (((lane >> 4) & 1) << 3);
                int c16 = ks*2 + ((lane >> 3) & 1);
                uint32_t off = SWZ((uint32_t)(row * 128 + c16 * 16));
                uint32_t t0, t1, t2, t3;
                ldsm_x4(Bs + off, t0, t1, t2, t3);
                bf[jj*2][0] = t0; bf[jj*2][1] = t1;
                bf[jj*2+1][0] = t2; bf[jj*2+1][1] = t3;
            }
            #pragma unroll
            for (int i = 0; i < 4; i++)
                #pragma unroll
                for (int j = 0; j < 4; j++)
                    mma16816(acc[i][j], af[i], bf[j]);
        }
        __syncthreads();
    }

    // ---- epilogue ----
    int mrow = bm + wm*64;
    int ncol = bn + wn*32;
    #pragma unroll
    for (int i = 0; i < 4; i++) {
        #pragma unroll
        for (int j = 0; j < 4; j++) {
            int rg = mrow + i*16 + (lane >> 2);
            int cg = ncol + j*8 + 2*(lane & 3);
            float b0v = bias[cg], b1v = bias[cg + 1];
            float v0 = acc[i][j][0] + b0v, v1 = acc[i][j][1] + b1v;
            float v2 = acc[i][j][2] + b0v, v3 = acc[i][j][3] + b1v;
            size_t a0 = (size_t)rg * N + cg;
            size_t a1 = (size_t)(rg + 8) * N + cg;
            if (EPI == 1) {
                float2 q0 = *(const float2*)(res + a0);
                float2 q1 = *(const float2*)(res + a1);
                v0 += q0.x; v1 += q0.y; v2 += q1.x; v3 += q1.y;
                *(float2*)(C + a0) = make_float2(v0, v1);
                *(float2*)(C + a1) = make_float2(v2, v3);
            }
            if (EPI == 2) {
                v0 = 0.5f * v0 * (1.0f + erff(v0 * 0.70710678118654752f));
                v1 = 0.5f * v1 * (1.0f + erff(v1 * 0.70710678118654752f));
                v2 = 0.5f * v2 * (1.0f + erff(v2 * 0.70710678118654752f));
                v3 = 0.5f * v3 * (1.0f + erff(v3 * 0.70710678118654752f));
                *(uint32_t*)(Co + a0) = pack2h(v0, v1);
                *(uint32_t*)(Co + a1) = pack2h(v2, v3);
            }
            if (EPI == 3) {
                float sc = (cg < EMBED) ? QSCALE : 1.0f;
                *(uint32_t*)(Co + a0) = pack2h(v0 * sc, v1 * sc);
                *(uint32_t*)(Co + a1) = pack2h(v2 * sc, v3 * sc);
            }
        }
    }
}

// ================= Flash attention (HMMA fp16, causal, exp2) =================
// CTA: 128 q rows, 64-key tiles. 8 warps x 16 rows.
// smem: Q 16K | 2 stages x {K,V} 8K each = 32K. Total 48K -> 2 CTAs/SM.
#define FA_Q 0u
#define FA_ST 16384u
#define FA_STB 16384u
#define KF(arr, j) (&(arr)[(((j) >> 1) << 2) + (((j) & 1) << 1)])

__global__ void __launch_bounds__(256, 2) fattn_kernel(
    const __half* __restrict__ qkv,
    __half* __restrict__ att)
{
    extern __shared__ char sm_[];
    uint32_t sb = smem_u32(sm_);
    int tid = threadIdx.x, lane = tid & 31, w = tid >> 5;
    int qblk = blockIdx.x, h = blockIdx.y, b = blockIdx.z;
    int q0 = qblk * 128;
    int ntiles = 2 * (qblk + 1);

    int cc = tid & 7, rr = tid >> 3;
    const char* base = (const char*)qkv + ((size_t)(b*SEQ)*3072 + h*64 + cc*8) * 2;

    // ---- Q load ----
    #pragma unroll
    for (int i = 0; i < 4; i++) {
        int r = rr + 32*i;
        size_t go = (size_t)(q0 + r) * 6144;
        uint32_t d = SWZ((uint32_t)(r * 128 + cc * 16));
        CP16(sb + FA_Q + d, base + go);
    }
    CP_COMMIT();

    // ---- prefetch K/V tile 0 ----
    {
        uint32_t st = sb + FA_ST;
        #pragma unroll
        for (int i = 0; i < 2; i++) {
            int r = rr + 32*i;
            size_t go = (size_t)r * 6144;
            uint32_t d = SWZ((uint32_t)(r * 128 + cc * 16));
            CP16(st + 0    + d, base + go + 2048);   // K
            CP16(st + 8192 + d, base + go + 4096);   // V
        }
        CP_COMMIT();
    }

    asm volatile("cp.async.wait_group 1;" ::: "memory");  // Q done
    __syncthreads();

    // ---- Q fragments ----
    uint32_t qf[4][4];
    #pragma unroll
    for (int ks = 0; ks < 4; ks++) {
        int row = w*16 + (lane & 15);
        int c16 = ks*2 + (lane >> 4);
        uint32_t off = SWZ((uint32_t)(row * 128 + c16 * 16));
        ldsm_x4(sb + FA_Q + off, qf[ks][0], qf[ks][1], qf[ks][2], qf[ks][3]);
    }

    float o[8][4];
    #pragma unroll
    for (int j = 0; j < 8; j++)
        #pragma unroll
        for (int q = 0; q < 4; q++) o[j][q] = 0.f;
    float m0 = -INFINITY, m1 = -INFINITY, l0 = 0.f, l1 = 0.f;
    int qg0 = q0 + w*16 + (lane >> 2);
    int qg1 = qg0 + 8;
    int wmin = q0 + w*16, wmax = wmin + 15;

    for (int kt = 0; kt < ntiles; kt++) {
        int k0 = kt * 64;
        if (kt + 1 < ntiles) {
            uint32_t st = sb + FA_ST + (uint32_t)((kt + 1) & 1) * FA_STB;
            #pragma unroll
            for (int i = 0; i < 2; i++) {
                int r = rr + 32*i;
                size_t go = (size_t)((kt + 1) * 64 + r) * 6144;
                uint32_t d = SWZ((uint32_t)(r * 128 + cc * 16));
                CP16(st + 0    + d, base + go + 2048);
                CP16(st + 8192 + d, base + go + 4096);
            }
            CP_COMMIT();
            asm volatile("cp.async.wait_group 1;" ::: "memory");
        } else {
            asm volatile("cp.async.wait_group 0;" ::: "memory");
        }
        __syncthreads();

        if (k0 <= wmax) {
            uint32_t st = sb + FA_ST + (uint32_t)(kt & 1) * FA_STB;

            // ---- S = Q @ K^T ----
            float s[8][4];
            #pragma unroll
            for (int j = 0; j < 8; j++)
                #pragma unroll
                for (int q = 0; q < 4; q++) s[j][q] = 0.f;

            #pragma unroll
            for (int ks = 0; ks < 4; ks++) {
                uint32_t kh[16];
                #pragma unroll
                for (int jj = 0; jj < 4; jj++) {
                    int row = jj*16 + (lane & 7) + (((lane >> 4) & 1) << 3);
                    int c16 = ks*2 + ((lane >> 3) & 1);
                    uint32_t off = SWZ((uint32_t)(row * 128 + c16 * 16));
                    ldsm_x4(st + off, kh[jj*4], kh[jj*4+1], kh[jj*4+2], kh[jj*4+3]);
                }
                #pragma unroll
                for (int j = 0; j < 8; j++) mma16816(s[j], qf[ks], KF(kh, j));
            }

            // ---- causal mask ----
            if (k0 + 63 > wmin) {
                int cb = k0 + 2*(lane & 3);
                #pragma unroll
                for (int j = 0; j < 8; j++) {
                    int c0 = cb + j*8, c1 = c0 + 1;
                    if (c0 > qg0) s[j][0] = -INFINITY;
                    if (c1 > qg0) s[j][1] = -INFINITY;
                    if (c0 > qg1) s[j][2] = -INFINITY;
                    if (c1 > qg1) s[j][3] = -INFINITY;
                }
            }

            // ---- online softmax (base-2) ----
            float tm0 = s[0][0], tm1 = s[0][2];
            #pragma unroll
            for (int j = 0; j < 8; j++) {
                tm0 = fmaxf(tm0, fmaxf(s[j][0], s[j][1]));
                tm1 = fmaxf(tm1, fmaxf(s[j][2], s[j][3]));
            }
            tm0 = fmaxf(tm0, __shfl_xor_sync(0xffffffffu, tm0, 1));
            tm0 = fmaxf(tm0, __shfl_xor_sync(0xffffffffu, tm0, 2));
            tm1 = fmaxf(tm1, __shfl_xor_sync(0xffffffffu, tm1, 1));
            tm1 = fmaxf(tm1, __shfl_xor_sync(0xffffffffu, tm1, 2));

            float nm0 = fmaxf(m0, tm0), nm1 = fmaxf(m1, tm1);
            float a0 = ex2f(m0 - nm0), a1 = ex2f(m1 - nm1);
            m0 = nm0; m1 = nm1;

            float sum0 = 0.f, sum1 = 0.f;
            #pragma unroll
            for (int j = 0; j < 8; j++) {
                s[j][0] = ex2f(s[j][0] - nm0); sum0 += s[j][0];
                s[j][1] = ex2f(s[j][1] - nm0); sum0 += s[j][1];
                s[j][2] = ex2f(s[j][2] - nm1); sum1 += s[j][2];
                s[j][3] = ex2f(s[j][3] - nm1); sum1 += s[j][3];
            }
            sum0 += __shfl_xor_sync(0xffffffffu, sum0, 1);
            sum0 += __shfl_xor_sync(0xffffffffu, sum0, 2);
            sum1 += __shfl_xor_sync(0xffffffffu, sum1, 1);
            sum1 += __shfl_xor_sync(0xffffffffu, sum1, 2);
            l0 = l0 * a0 + sum0;
            l1 = l1 * a1 + sum1;

            #pragma unroll
            for (int j = 0; j < 8; j++) {
                o[j][0] *= a0; o[j][1] *= a0;
                o[j][2] *= a1; o[j][3] *= a1;
            }

            // ---- P fragments (fp16) ----
            uint32_t pf[4][4];
            #pragma unroll
            for (int ks = 0; ks < 4; ks++) {
                pf[ks][0] = pack2h(s[2*ks][0],   s[2*ks][1]);
                pf[ks][1] = pack2h(s[2*ks][2],   s[2*ks][3]);
                pf[ks][2] = pack2h(s[2*ks+1][0], s[2*ks+1][1]);
                pf[ks][3] = pack2h(s[2*ks+1][2], s[2*ks+1][3]);
            }

            // ---- O += P @ V ----
            #pragma unroll
            for (int ks = 0; ks < 4; ks++) {
                uint32_t vh[16];
                #pragma unroll
                for (int nn = 0; nn < 4; nn++) {
                    int key = ks*16 + (lane & 7) + (((lane >> 3) & 1) << 3);
                    int dim = nn*16 + ((lane >> 4) << 3);
                    uint32_t off = SWZ((uint32_t)(key * 128 + dim * 2));
                    ldsm_x4_t(st + 8192 + off, vh[nn*4], vh[nn*4+1], vh[nn*4+2], vh[nn*4+3]);
                }
                #pragma unroll
                for (int j = 0; j < 8; j++) mma16816(o[j], pf[ks], KF(vh, j));
            }
        }
        __syncthreads();
    }

    // ---- epilogue: O/l -> fp16 ----
    float inv0 = 1.0f / l0, inv1 = 1.0f / l1;
    size_t t0 = (size_t)(b*SEQ + qg0) * EMBED + h*64;
    size_t t1 = t0 + (size_t)8 * EMBED;
    #pragma unroll
    for (int j = 0; j < 8; j++) {
        int dd = j*8 + 2*(lane & 3);
        *(uint32_t*)(att + t0 + dd) = pack2h(o[j][0]*inv0, o[j][1]*inv0);
        *(uint32_t*)(att + t1 + dd) = pack2h(o[j][2]*inv1, o[j][3]*inv1);
    }
}

// ================= launch =================
extern "C" void kernel_launch(void* const* d_in, const int* in_sizes, int n_in,
                              void* d_out, int out_size)
{
    const float* x      = (const float*)d_in[0];
    const float* ln1_w  = (const float*)d_in[1];
    const float* ln1_b  = (const float*)d_in[2];
    const float* qkv_w  = (const float*)d_in[3];
    const float* qkv_b  = (const float*)d_in[4];
    const float* proj_w = (const float*)d_in[5];
    const float* proj_b = (const float*)d_in[6];
    const float* ln2_w  = (const float*)d_in[7];
    const float* ln2_b  = (const float*)d_in[8];
    const float* fc1_w  = (const float*)d_in[9];
    const float* fc1_b  = (const float*)d_in[10];
    const float* fc2_w  = (const float*)d_in[11];
    const float* fc2_b  = (const float*)d_in[12];
    float* out = (float*)d_out;

    float *x1;
    __half *xn, *qkv, *att, *hbuf, *qw, *pw, *f1w, *f2w;
    cudaGetSymbolAddress((void**)&x1,   g_x1);
    cudaGetSymbolAddress((void**)&xn,   g_xn);
    cudaGetSymbolAddress((void**)&qkv,  g_qkv);
    cudaGetSymbolAddress((void**)&att,  g_att);
    cudaGetSymbolAddress((void**)&hbuf, g_h);
    cudaGetSymbolAddress((void**)&qw,   g_qkvw);
    cudaGetSymbolAddress((void**)&pw,   g_projw);
    cudaGetSymbolAddress((void**)&f1w,  g_fc1w);
    cudaGetSymbolAddress((void**)&f2w,  g_fc2w);

    int gemm_smem = 3 * STG;   // 98304 -> 2 CTAs/SM
    cudaFuncSetAttribute(mm_kernel<1>, cudaFuncAttributeMaxDynamicSharedMemorySize, gemm_smem);
    cudaFuncSetAttribute(mm_kernel<2>, cudaFuncAttributeMaxDynamicSharedMemorySize, gemm_smem);
    cudaFuncSetAttribute(mm_kernel<3>, cudaFuncAttributeMaxDynamicSharedMemorySize, gemm_smem);
    int attn_smem = 16384 + 2 * 16384;   // 49152 -> 2 CTAs/SM
    cudaFuncSetAttribute(fattn_kernel, cudaFuncAttributeMaxDynamicSharedMemorySize, attn_smem);

    // weight conversion
    cvt_kernel<<<(3*EMBED*EMBED/4 + 255)/256, 256>>>(qkv_w,  qw,  3*EMBED*EMBED/4);
    cvt_kernel<<<(EMBED*EMBED/4   + 255)/256, 256>>>(proj_w, pw,  EMBED*EMBED/4);
    cvt_kernel<<<(HIDDEN*EMBED/4  + 255)/256, 256>>>(fc1_w,  f1w, HIDDEN*EMBED/4);
    cvt_kernel<<<(EMBED*HIDDEN/4  + 255)/256, 256>>>(fc2_w,  f2w, EMBED*HIDDEN/4);

    // 1. LN1 -> xn (fp16)
    ln_kernel<<<NTOK, 256>>>(x, ln1_w, ln1_b, xn);
    // 2. qkv = xn @ qkv_w^T + qkv_b  (q pre-scaled, fp16)
    mm_kernel<3><<<dim3(NTOK/128, 3*EMBED/128), 256, gemm_smem>>>(
        xn, qw, qkv_b, nullptr, nullptr, qkv, NTOK, 3*EMBED, EMBED);
    // 3. attention -> att (fp16)
    fattn_kernel<<<dim3(SEQ/128, HEADS, BATCH), 256, attn_smem>>>(qkv, att);
    // 4. x1 = att @ proj_w^T + proj_b + x  (fp32)
    mm_kernel<1><<<dim3(NTOK/128, EMBED/128), 256, gemm_smem>>>(
        att, pw, proj_b, x, x1, nullptr, NTOK, EMBED, EMBED);
    // 5. LN2 -> xn (fp16)
    ln_kernel<<<NTOK, 256>>>(x1, ln2_w, ln2_b, xn);
    // 6. h = gelu(xn @ fc1_w^T + fc1_b) -> fp16
    mm_kernel<2><<<dim3(NTOK/128, HIDDEN/128), 256, gemm_smem>>>(
        xn, f1w, fc1_b, nullptr, nullptr, hbuf, NTOK, HIDDEN, EMBED);
    // 7. out = h @ fc2_w^T + fc2_b + x1  (fp32)
    mm_kernel<1><<<dim3(NTOK/128, EMBED/128), 256, gemm_smem>>>(
        hbuf, f2w, fc2_b, x1, out, nullptr, NTOK, EMBED, HIDDEN);
}